// round 6
// baseline (speedup 1.0000x reference)
#include <cuda_runtime.h>
#include <math.h>

// Problem constants
#define BATCH 4
#define SEQ   2048
#define EMBD  1024
#define NH    16
#define DKH   64
#define BH    (BATCH * NH)      // 64
#define BSQ   (BATCH * SEQ)     // 8192

#define QKV_ELEMS  (BATCH * NH * SEQ * DKH)          // 8,388,608
#define PRED_ELEMS (BSQ * EMBD)                      // 8,388,608
#define ATTN_ELEMS ((size_t)BH * SEQ * SEQ)          // 268,435,456

// Scratch (allocation-free: device globals)
__device__ float g_q[QKV_ELEMS];        // [B,H,S,D]
__device__ float g_k[QKV_ELEMS];        // [B,H,S,D]
__device__ float g_v[QKV_ELEMS];        // [B,H,S,D]
__device__ float g_pred[PRED_ELEMS];    // [B,S,H*D]
__device__ float g_attn_fb[ATTN_ELEMS]; // fallback attn scratch [B,H,S,S]
__device__ int   g_mask_mode;           // 0=uint8, 1=int32, 2=float32

// ---------------------------------------------------------------------------
// Kernel 0: detect mask element dtype from its bit patterns.
// int32 bool: every 32-bit word is 0 or 1.
// float32 bool: every word is 0 or 0x3f800000.
// uint8 bool: words contain ones in arbitrary byte lanes (10% density ->
//             certainty within the first 256KB scanned).
// Deterministic, graph-capturable, ~5us.
// ---------------------------------------------------------------------------
__global__ void detect_mask_kernel(const unsigned int* __restrict__ m)
{
    __shared__ int s01, sf;
    if (threadIdx.x == 0) { s01 = 1; sf = 1; }
    __syncthreads();
    int a01 = 1, af = 1;
    for (int i = threadIdx.x; i < 65536; i += blockDim.x) {
        const unsigned int w = m[i];
        if (w > 1u) a01 = 0;
        if (w != 0u && w != 0x3f800000u) af = 0;
    }
    if (!a01) atomicAnd(&s01, 0);
    if (!af)  atomicAnd(&sf, 0);
    __syncthreads();
    if (threadIdx.x == 0) g_mask_mode = s01 ? 1 : (sf ? 2 : 0);
}

// ---------------------------------------------------------------------------
// Kernel 1: fused QKV projection.  z selects (Q,W_Q)->g_q etc.
// GEMM M=8192, N=1024, K=1024, output scattered to [B,H,S,D].
// 64x64 block tile, 256 threads, 4x4 per thread, k-step 16.
// ---------------------------------------------------------------------------
__global__ __launch_bounds__(256) void proj_kernel(
    const float* __restrict__ Qin, const float* __restrict__ Kin,
    const float* __restrict__ Vin,
    const float* __restrict__ WQ, const float* __restrict__ WK,
    const float* __restrict__ WV)
{
    const float* A; const float* W; float* O;
    if (blockIdx.z == 0)      { A = Qin; W = WQ; O = g_q; }
    else if (blockIdx.z == 1) { A = Kin; W = WK; O = g_k; }
    else                      { A = Vin; W = WV; O = g_v; }

    __shared__ float As[16][68];   // As[k][m]
    __shared__ float Bs[16][68];   // Bs[k][n]

    const int tid = threadIdx.x;
    const int tx = tid & 15, ty = tid >> 4;
    const int m0 = blockIdx.y * 64, n0 = blockIdx.x * 64;
    const int arow = tid >> 2,  acol = (tid & 3) * 4;
    const int brow = tid >> 4,  bcol = (tid & 15) * 4;

    float acc[4][4] = {};

    for (int kt = 0; kt < EMBD; kt += 16) {
        float4 av = *(const float4*)&A[(size_t)(m0 + arow) * EMBD + kt + acol];
        As[acol + 0][arow] = av.x;
        As[acol + 1][arow] = av.y;
        As[acol + 2][arow] = av.z;
        As[acol + 3][arow] = av.w;
        float4 bv = *(const float4*)&W[(size_t)(kt + brow) * EMBD + n0 + bcol];
        *(float4*)&Bs[brow][bcol] = bv;
        __syncthreads();
        #pragma unroll
        for (int kk = 0; kk < 16; ++kk) {
            const float4 a = *(const float4*)&As[kk][ty * 4];
            const float4 b = *(const float4*)&Bs[kk][tx * 4];
            const float ar[4] = {a.x, a.y, a.z, a.w};
            const float br[4] = {b.x, b.y, b.z, b.w};
            #pragma unroll
            for (int i = 0; i < 4; ++i)
                #pragma unroll
                for (int j = 0; j < 4; ++j)
                    acc[i][j] = fmaf(ar[i], br[j], acc[i][j]);
        }
        __syncthreads();
    }

    #pragma unroll
    for (int i = 0; i < 4; ++i) {
        const int m = m0 + ty * 4 + i;
        const int b = m >> 11, s = m & (SEQ - 1);
        #pragma unroll
        for (int j = 0; j < 4; ++j) {
            const int n = n0 + tx * 4 + j;
            const int h = n >> 6, d = n & (DKH - 1);
            O[(((size_t)(b * NH + h)) * SEQ + s) * DKH + d] = acc[i][j];
        }
    }
}

// ---------------------------------------------------------------------------
// Kernel 2: masked scores.  Per (b,h): S[sq,sk] = (q.k)/8, masked -> -1e9.
// GEMM M=N=2048, K=64. B operand (K matrix) loaded transposed.
// Mask dtype resolved at runtime via g_mask_mode (epilogue only).
// ---------------------------------------------------------------------------
__global__ __launch_bounds__(256) void scores_kernel(
    const void* __restrict__ mask, float* __restrict__ attn)
{
    const int z = blockIdx.z;          // b*NH + h
    const int b = z >> 4;
    const float* qb = g_q + (size_t)z * SEQ * DKH;
    const float* kb = g_k + (size_t)z * SEQ * DKH;

    __shared__ float As[16][68];   // As[d][sq]
    __shared__ float Bs[16][68];   // Bs[d][sk]

    const int tid = threadIdx.x;
    const int tx = tid & 15, ty = tid >> 4;
    const int m0 = blockIdx.y * 64, n0 = blockIdx.x * 64;
    const int row = tid >> 2, col = (tid & 3) * 4;

    float acc[4][4] = {};

    for (int kt = 0; kt < DKH; kt += 16) {
        float4 av = *(const float4*)&qb[(size_t)(m0 + row) * DKH + kt + col];
        As[col + 0][row] = av.x;
        As[col + 1][row] = av.y;
        As[col + 2][row] = av.z;
        As[col + 3][row] = av.w;
        float4 bv = *(const float4*)&kb[(size_t)(n0 + row) * DKH + kt + col];
        Bs[col + 0][row] = bv.x;
        Bs[col + 1][row] = bv.y;
        Bs[col + 2][row] = bv.z;
        Bs[col + 3][row] = bv.w;
        __syncthreads();
        #pragma unroll
        for (int kk = 0; kk < 16; ++kk) {
            const float4 a = *(const float4*)&As[kk][ty * 4];
            const float4 bq = *(const float4*)&Bs[kk][tx * 4];
            const float ar[4] = {a.x, a.y, a.z, a.w};
            const float br[4] = {bq.x, bq.y, bq.z, bq.w};
            #pragma unroll
            for (int i = 0; i < 4; ++i)
                #pragma unroll
                for (int j = 0; j < 4; ++j)
                    acc[i][j] = fmaf(ar[i], br[j], acc[i][j]);
        }
        __syncthreads();
    }

    const int mode = g_mask_mode;
    const unsigned char* m8  = (const unsigned char*)mask;
    const int*           m32 = (const int*)mask;
    const float*         mf  = (const float*)mask;

    #pragma unroll
    for (int i = 0; i < 4; ++i) {
        const int m = m0 + ty * 4 + i;
        const size_t mbase = ((size_t)b * SEQ + m) * SEQ;
        float* orow = attn + (((size_t)z * SEQ) + m) * SEQ;
        #pragma unroll
        for (int j = 0; j < 4; ++j) {
            const int n = n0 + tx * 4 + j;
            float v = acc[i][j] * 0.125f;          // 1/sqrt(64)
            bool masked;
            if (mode == 1)      masked = (m32[mbase + n] != 0);
            else if (mode == 2) masked = (mf[mbase + n] != 0.0f);
            else                masked = (m8[mbase + n] != 0);
            if (masked) v = -1e9f;
            orow[n] = v;
        }
    }
}

// ---------------------------------------------------------------------------
// Kernel 3: row softmax over 2048 keys.  One block (256 thr) per row.
// Row held entirely in registers (8 floats/thread): 1 read + 1 write pass.
// ---------------------------------------------------------------------------
__global__ __launch_bounds__(256) void softmax_kernel(float* __restrict__ attn)
{
    float* p = attn + (size_t)blockIdx.x * SEQ;
    const int t = threadIdx.x;

    float v[8];
    float m = -3.4e38f;
    #pragma unroll
    for (int j = 0; j < 8; ++j) {
        v[j] = p[t + j * 256];
        m = fmaxf(m, v[j]);
    }

    __shared__ float red[8];
    __shared__ float bmax, bsum;
    #pragma unroll
    for (int o = 16; o > 0; o >>= 1) m = fmaxf(m, __shfl_xor_sync(0xffffffffu, m, o));
    if ((t & 31) == 0) red[t >> 5] = m;
    __syncthreads();
    if (t == 0) {
        float mm = red[0];
        #pragma unroll
        for (int i = 1; i < 8; ++i) mm = fmaxf(mm, red[i]);
        bmax = mm;
    }
    __syncthreads();
    m = bmax;

    float s = 0.f;
    #pragma unroll
    for (int j = 0; j < 8; ++j) {
        v[j] = __expf(v[j] - m);
        s += v[j];
    }
    __syncthreads();   // protect red[] reuse
    #pragma unroll
    for (int o = 16; o > 0; o >>= 1) s += __shfl_xor_sync(0xffffffffu, s, o);
    if ((t & 31) == 0) red[t >> 5] = s;
    __syncthreads();
    if (t == 0) {
        float ss = red[0];
        #pragma unroll
        for (int i = 1; i < 8; ++i) ss += red[i];
        bsum = ss;
    }
    __syncthreads();
    const float inv = 1.0f / bsum;

    #pragma unroll
    for (int j = 0; j < 8; ++j) p[t + j * 256] = v[j] * inv;
}

// ---------------------------------------------------------------------------
// Kernel 4: pred = attn @ v.  Per (b,h): M=2048, N=64, K=2048.
// Output scattered to [B,S,H*D] layout for the FC GEMM.
// ---------------------------------------------------------------------------
__global__ __launch_bounds__(256) void av_kernel(const float* __restrict__ attn)
{
    const int z = blockIdx.z;          // b*NH + h
    const int b = z >> 4, h = z & 15;
    const float* Ab = attn + (size_t)z * SEQ * SEQ;
    const float* Vb = g_v + (size_t)z * SEQ * DKH;

    __shared__ float As[16][68];
    __shared__ float Bs[16][68];

    const int tid = threadIdx.x;
    const int tx = tid & 15, ty = tid >> 4;
    const int m0 = blockIdx.y * 64;
    const int arow = tid >> 2, acol = (tid & 3) * 4;
    const int brow = tid >> 4, bcol = (tid & 15) * 4;

    float acc[4][4] = {};

    for (int kt = 0; kt < SEQ; kt += 16) {
        float4 av = *(const float4*)&Ab[(size_t)(m0 + arow) * SEQ + kt + acol];
        As[acol + 0][arow] = av.x;
        As[acol + 1][arow] = av.y;
        As[acol + 2][arow] = av.z;
        As[acol + 3][arow] = av.w;
        float4 bv = *(const float4*)&Vb[(size_t)(kt + brow) * DKH + bcol];
        *(float4*)&Bs[brow][bcol] = bv;
        __syncthreads();
        #pragma unroll
        for (int kk = 0; kk < 16; ++kk) {
            const float4 a = *(const float4*)&As[kk][ty * 4];
            const float4 bq = *(const float4*)&Bs[kk][tx * 4];
            const float ar[4] = {a.x, a.y, a.z, a.w};
            const float br[4] = {bq.x, bq.y, bq.z, bq.w};
            #pragma unroll
            for (int i = 0; i < 4; ++i)
                #pragma unroll
                for (int j = 0; j < 4; ++j)
                    acc[i][j] = fmaf(ar[i], br[j], acc[i][j]);
        }
        __syncthreads();
    }

    #pragma unroll
    for (int i = 0; i < 4; ++i) {
        const int m = m0 + ty * 4 + i;
        #pragma unroll
        for (int j = 0; j < 4; ++j) {
            const int n = tx * 4 + j;
            g_pred[((size_t)(b * SEQ + m)) * EMBD + h * DKH + n] = acc[i][j];
        }
    }
}

// ---------------------------------------------------------------------------
// Kernel 5: out = pred @ W_fc.  M=8192, N=1024, K=1024.
// ---------------------------------------------------------------------------
__global__ __launch_bounds__(256) void fc_kernel(
    const float* __restrict__ Wfc, float* __restrict__ out)
{
    __shared__ float As[16][68];
    __shared__ float Bs[16][68];

    const int tid = threadIdx.x;
    const int tx = tid & 15, ty = tid >> 4;
    const int m0 = blockIdx.y * 64, n0 = blockIdx.x * 64;
    const int arow = tid >> 2, acol = (tid & 3) * 4;
    const int brow = tid >> 4, bcol = (tid & 15) * 4;

    float acc[4][4] = {};

    for (int kt = 0; kt < EMBD; kt += 16) {
        float4 av = *(const float4*)&g_pred[(size_t)(m0 + arow) * EMBD + kt + acol];
        As[acol + 0][arow] = av.x;
        As[acol + 1][arow] = av.y;
        As[acol + 2][arow] = av.z;
        As[acol + 3][arow] = av.w;
        float4 bv = *(const float4*)&Wfc[(size_t)(kt + brow) * EMBD + n0 + bcol];
        *(float4*)&Bs[brow][bcol] = bv;
        __syncthreads();
        #pragma unroll
        for (int kk = 0; kk < 16; ++kk) {
            const float4 a = *(const float4*)&As[kk][ty * 4];
            const float4 bq = *(const float4*)&Bs[kk][tx * 4];
            const float ar[4] = {a.x, a.y, a.z, a.w};
            const float br[4] = {bq.x, bq.y, bq.z, bq.w};
            #pragma unroll
            for (int i = 0; i < 4; ++i)
                #pragma unroll
                for (int j = 0; j < 4; ++j)
                    acc[i][j] = fmaf(ar[i], br[j], acc[i][j]);
        }
        __syncthreads();
    }

    #pragma unroll
    for (int i = 0; i < 4; ++i) {
        const int m = m0 + ty * 4 + i;
        #pragma unroll
        for (int j = 0; j < 4; ++j) {
            const int n = n0 + tx * 4 + j;
            out[(size_t)m * EMBD + n] = acc[i][j];
        }
    }
}

// ---------------------------------------------------------------------------
extern "C" void kernel_launch(void* const* d_in, const int* in_sizes, int n_in,
                              void* d_out, int out_size)
{
    const float* Q  = (const float*)d_in[0];
    const float* K  = (const float*)d_in[1];
    const float* V  = (const float*)d_in[2];
    const void*  mask = d_in[3];
    const float* WQ  = (const float*)d_in[4];
    const float* WK  = (const float*)d_in[5];
    const float* WV  = (const float*)d_in[6];
    const float* Wfc = (const float*)d_in[7];
    float* out = (float*)d_out;

    // attn target: second tuple element of the reference output if the harness
    // expects it, otherwise device-global scratch.
    float* attn_ptr;
    if (out_size >= (int)(PRED_ELEMS + ATTN_ELEMS)) {
        attn_ptr = out + PRED_ELEMS;
    } else {
        void* p = nullptr;
        cudaGetSymbolAddress(&p, g_attn_fb);
        attn_ptr = (float*)p;
    }

    detect_mask_kernel<<<1, 1024>>>((const unsigned int*)mask);
    proj_kernel<<<dim3(EMBD / 64, BSQ / 64, 3), 256>>>(Q, K, V, WQ, WK, WV);
    scores_kernel<<<dim3(SEQ / 64, SEQ / 64, BH), 256>>>(mask, attn_ptr);
    softmax_kernel<<<BH * SEQ, 256>>>(attn_ptr);
    av_kernel<<<dim3(1, SEQ / 64, BH), 256>>>(attn_ptr);
    fc_kernel<<<dim3(EMBD / 64, BSQ / 64, 1), 256>>>(Wfc, out);
}